// round 2
// baseline (speedup 1.0000x reference)
#include <cuda_runtime.h>
#include <cstdint>

#define BATCH   32768
#define NSITES  64
#define BD      32
#define NBULK   62
#define TPB     256
#define CPAD    1028          // floats per c-block in smem: 1024 + 4 pad (bank stagger)
#define BUFF    (2*CPAD)      // floats per site buffer

__device__ __forceinline__ void cp_async16(void* dst, const void* src) {
    uint32_t s = (uint32_t)__cvta_generic_to_shared(dst);
    asm volatile("cp.async.ca.shared.global [%0], [%1], 16;" :: "r"(s), "l"(src));
}
__device__ __forceinline__ void cp_commit() { asm volatile("cp.async.commit_group;"); }
template<int N>
__device__ __forceinline__ void cp_wait() { asm volatile("cp.async.wait_group %0;" :: "n"(N)); }

__global__ void __launch_bounds__(TPB, 1)
mps_kernel(const int*   __restrict__ conf,     // int32 configurations [BATCH][64]
           const float* __restrict__ left,
           const float* __restrict__ bulk,
           const float* __restrict__ right,
           float*       __restrict__ out)
{
    __shared__ __align__(16) float sbuf[2][BUFF + 8];
    __shared__ float lt_s[2 * BD];   // left_tensor [2][32]
    __shared__ float rt_s[BD * 2];   // right_tensor [32][2]

    const int tid = threadIdx.x;
    const int b   = blockIdx.x * TPB + tid;

    if (tid < 2 * BD) { lt_s[tid] = left[tid]; rt_s[tid] = right[tid]; }

    // ---- compress this sample's 64 int32 config values into a bitmask ----
    unsigned long long mask = 0;
    {
        const int4* cp4 = (const int4*)(conf + (size_t)b * NSITES);
        #pragma unroll
        for (int i = 0; i < NSITES / 4; i++) {
            int4 v = cp4[i];
            mask |= ((unsigned long long)(v.x & 1) << (4 * i))
                  | ((unsigned long long)(v.y & 1) << (4 * i + 1))
                  | ((unsigned long long)(v.z & 1) << (4 * i + 2))
                  | ((unsigned long long)(v.w & 1) << (4 * i + 3));
        }
    }

    // ---- stage site 0 matrices (2048 floats) into sbuf[0] via cp.async ----
    {
        const float* src = bulk;
        #pragma unroll
        for (int k2 = 0; k2 < 2; k2++) {
            int k  = tid + k2 * TPB;         // 16B chunk id, 0..511
            int e0 = (k & 7) * 4;            // element within row
            int c  = (k >> 3) & 1;           // phys index
            int d  = k >> 4;                 // row
            cp_async16(&sbuf[0][c * CPAD + d * BD + e0], src + k * 4);
        }
        cp_commit();
    }
    __syncthreads();   // lt_s / rt_s visible

    // ---- init env from left_tensor[c0] ----
    float env[BD];
    {
        const int c0 = (int)(mask & 1ull);
        #pragma unroll
        for (int e = 0; e < BD; e++) env[e] = lt_s[c0 * BD + e];
    }

    // ---- chain over 62 bulk sites ----
    for (int s = 0; s < NBULK; s++) {
        if (s + 1 < NBULK) {
            // prefetch next site into other buffer
            const float* src  = bulk + (size_t)(s + 1) * 2048;
            float*       dbuf = sbuf[(s + 1) & 1];
            #pragma unroll
            for (int k2 = 0; k2 < 2; k2++) {
                int k  = tid + k2 * TPB;
                int e0 = (k & 7) * 4;
                int c  = (k >> 3) & 1;
                int d  = k >> 4;
                cp_async16(&dbuf[c * CPAD + d * BD + e0], src + k * 4);
            }
            cp_commit();
            cp_wait<1>();     // current site's group is complete
        } else {
            cp_wait<0>();
        }
        __syncthreads();

        const int    c   = (int)((mask >> (s + 1)) & 1ull);
        const float* mat = &sbuf[s & 1][c * CPAD];

        // env_new[e] = sum_d env[d] * M[d][e], packed f32x2 over e-pairs
        unsigned long long acc[BD / 2];
        #pragma unroll
        for (int d = 0; d < BD; d++) {
            unsigned int er = __float_as_uint(env[d]);
            unsigned long long ed2;
            asm("mov.b64 %0, {%1, %1};" : "=l"(ed2) : "r"(er));
            const ulonglong2* row = (const ulonglong2*)(mat + d * BD);
            #pragma unroll
            for (int j = 0; j < 8; j++) {
                ulonglong2 v = row[j];   // 4 floats: e = 4j .. 4j+3
                if (d == 0) {
                    asm("mul.rn.f32x2 %0, %1, %2;"
                        : "=l"(acc[2 * j])     : "l"(ed2), "l"(v.x));
                    asm("mul.rn.f32x2 %0, %1, %2;"
                        : "=l"(acc[2 * j + 1]) : "l"(ed2), "l"(v.y));
                } else {
                    asm("fma.rn.f32x2 %0, %1, %2, %0;"
                        : "+l"(acc[2 * j])     : "l"(ed2), "l"(v.x));
                    asm("fma.rn.f32x2 %0, %1, %2, %0;"
                        : "+l"(acc[2 * j + 1]) : "l"(ed2), "l"(v.y));
                }
            }
        }
        // unpack packed accumulators back into env
        #pragma unroll
        for (int j = 0; j < BD / 2; j++) {
            unsigned int lo, hi;
            asm("mov.b64 {%0, %1}, %2;" : "=r"(lo), "=r"(hi) : "l"(acc[j]));
            env[2 * j]     = __uint_as_float(lo);
            env[2 * j + 1] = __uint_as_float(hi);
        }
        __syncthreads();   // protect buffer before next prefetch overwrites it
    }

    // ---- final contraction with right_tensor[:, c63] ----
    const int cN = (int)((mask >> 63) & 1ull);
    float psi = 0.0f;
    #pragma unroll
    for (int d = 0; d < BD; d++) psi += env[d] * rt_s[d * 2 + cN];
    out[b] = psi;
}

extern "C" void kernel_launch(void* const* d_in, const int* in_sizes, int n_in,
                              void* d_out, int out_size) {
    const int*   conf  = (const int*)d_in[0];
    const float* left  = (const float*)d_in[1];
    const float* bulk  = (const float*)d_in[2];
    const float* right = (const float*)d_in[3];
    float*       out   = (float*)d_out;

    mps_kernel<<<BATCH / TPB, TPB>>>(conf, left, bulk, right, out);
}

// round 4
// speedup vs baseline: 3.3264x; 3.3264x over previous
#include <cuda_runtime.h>
#include <cuda_bf16.h>
#include <cstdint>

#define BATCH   32768
#define NSITES  64
#define NBULK   62
#define TPB     128
#define NCTA    (BATCH / TPB)          // 256
#define ROWB    80                     // bytes per SMEM tile row (32 bf16 + 8 pad) — LDSM conflict-free
#define TILE_BYTES (32 * ROWB)         // 2560
#define SITE_BYTES (4 * TILE_BYTES)    // M0h, M0l, M1h, M1l = 10240

// Precomputed bf16 hi/lo B tiles for every site, LDSM-ready layout [n][k] rows of 80B.
__device__ __align__(256) unsigned char g_btiles[NBULK * SITE_BYTES];

// ---------------- helpers ----------------
__device__ __forceinline__ uint32_t smem_u32(const void* p) {
    uint32_t a;
    asm("{ .reg .u64 t; cvta.to.shared.u64 t, %1; cvt.u32.u64 %0, t; }" : "=r"(a) : "l"(p));
    return a;
}
__device__ __forceinline__ void cp_async16(uint32_t dst, const void* src) {
    asm volatile("cp.async.ca.shared.global [%0], [%1], 16;" :: "r"(dst), "l"(src));
}
__device__ __forceinline__ void cp_commit() { asm volatile("cp.async.commit_group;"); }
template<int N> __device__ __forceinline__ void cp_wait() { asm volatile("cp.async.wait_group %0;" :: "n"(N)); }

__device__ __forceinline__ void ldsm_x4(uint32_t* r, uint32_t addr) {
    asm volatile("ldmatrix.sync.aligned.m8n8.x4.shared.b16 {%0,%1,%2,%3}, [%4];"
        : "=r"(r[0]), "=r"(r[1]), "=r"(r[2]), "=r"(r[3]) : "r"(addr));
}
// D += A(bf16x2 x4) * B(bf16x2 x2), fp32 accum
__device__ __forceinline__ void mma16816(float* d, const uint32_t* a, uint32_t b0, uint32_t b1) {
    asm volatile("mma.sync.aligned.m16n8k16.row.col.f32.bf16.bf16.f32 "
        "{%0,%1,%2,%3}, {%4,%5,%6,%7}, {%8,%9}, {%0,%1,%2,%3};"
        : "+f"(d[0]), "+f"(d[1]), "+f"(d[2]), "+f"(d[3])
        : "r"(a[0]), "r"(a[1]), "r"(a[2]), "r"(a[3]), "r"(b0), "r"(b1));
}
// pack {lo, hi} floats -> bf16x2 (lo in low 16 bits)
__device__ __forceinline__ uint32_t packbf(float lo, float hi) {
    uint32_t r;
    asm("cvt.rn.bf16x2.f32 %0, %1, %2;" : "=r"(r) : "f"(hi), "f"(lo));
    return r;
}

// ---------------- prep: fp32 bulk -> bf16 hi/lo B tiles [n][k] rows (80B pitch) ----------------
__global__ void prep_kernel(const float* __restrict__ bulk) {
    int s = blockIdx.x;
    const float* base = bulk + s * 2048;            // [d][c][e]
    for (int idx = threadIdx.x; idx < 4096; idx += blockDim.x) {
        int t    = idx >> 10;                        // tile: 0=M0h 1=M0l 2=M1h 3=M1l
        int c    = t >> 1;
        int half = t & 1;
        int rem  = idx & 1023;
        int n    = rem >> 5;                         // e
        int k    = rem & 31;                         // d
        float x  = base[(k * 2 + c) * 32 + n];
        __nv_bfloat16 bh = __float2bfloat16(x);
        __nv_bfloat16 v  = half ? __float2bfloat16(x - __bfloat162float(bh)) : bh;
        *(__nv_bfloat16*)(g_btiles + (size_t)s * SITE_BYTES + t * TILE_BYTES + n * ROWB + k * 2) = v;
    }
}

// ---------------- main kernel ----------------
__global__ void __launch_bounds__(TPB, 2)
mps_mma_kernel(const int*   __restrict__ conf,
               const float* __restrict__ left,
               const float* __restrict__ right,
               float*       __restrict__ out)
{
    __shared__ __align__(16) unsigned char sb[2][SITE_BYTES];
    __shared__ unsigned long long masks_s[TPB];
    __shared__ float lt_s[64];
    __shared__ float rt_s[64];

    const int tid  = threadIdx.x;
    const int wid  = tid >> 5;
    const int lane = tid & 31;
    const int rowq = lane >> 2;       // 0..7
    const int q    = lane & 3;        // 0..3

    if (tid < 64) { lt_s[tid] = left[tid]; rt_s[tid] = right[tid]; }

    // per-sample config bitmask
    {
        unsigned long long mask = 0;
        const int4* cp4 = (const int4*)(conf + (size_t)(blockIdx.x * TPB + tid) * NSITES);
        #pragma unroll
        for (int i = 0; i < NSITES / 4; i++) {
            int4 v = cp4[i];
            mask |= ((unsigned long long)(v.x & 1) << (4 * i))
                  | ((unsigned long long)(v.y & 1) << (4 * i + 1))
                  | ((unsigned long long)(v.z & 1) << (4 * i + 2))
                  | ((unsigned long long)(v.w & 1) << (4 * i + 3));
        }
        masks_s[tid] = mask;
    }

    // prefetch site-0 tiles
    {
        uint32_t dst = smem_u32(&sb[0][0]);
        #pragma unroll
        for (int i = 0; i < 5; i++)
            cp_async16(dst + (tid + i * TPB) * 16, g_btiles + (tid + i * TPB) * 16);
        cp_commit();
    }
    __syncthreads();

    // masks of the 4 rows this thread's fragments touch: rowq, +8, +16, +24 (within warp's 32 samples)
    unsigned long long mr[4];
    #pragma unroll
    for (int k = 0; k < 4; k++) mr[k] = masks_s[wid * 32 + rowq + 8 * k];

    // env in D-fragment layout: env[mtile i][ntile j][r], rows: c0c1 -> rowq+16i, c2c3 -> rowq+16i+8
    float env[2][4][4];
    #pragma unroll
    for (int i = 0; i < 2; i++) {
        const int cA = (int)(mr[2 * i] & 1ull);
        const int cB = (int)(mr[2 * i + 1] & 1ull);
        #pragma unroll
        for (int j = 0; j < 4; j++) {
            int n0 = 8 * j + 2 * q;
            env[i][j][0] = lt_s[cA * 32 + n0];
            env[i][j][1] = lt_s[cA * 32 + n0 + 1];
            env[i][j][2] = lt_s[cB * 32 + n0];
            env[i][j][3] = lt_s[cB * 32 + n0 + 1];
        }
    }

    const uint32_t lds_off = (uint32_t)((lane & 7) * ROWB + (lane >> 3) * 16);

    for (int s = 0; s < NBULK; s++) {
        if (s + 1 < NBULK) {
            uint32_t dst = smem_u32(&sb[(s + 1) & 1][0]);
            const unsigned char* src = g_btiles + (size_t)(s + 1) * SITE_BYTES;
            #pragma unroll
            for (int i = 0; i < 5; i++)
                cp_async16(dst + (tid + i * TPB) * 16, src + (tid + i * TPB) * 16);
            cp_commit();
            cp_wait<1>();
        } else {
            cp_wait<0>();
        }
        __syncthreads();   // site-s tiles visible to all warps

        // split env -> A fragments (bf16 hi/lo), D-layout == A-layout reinterpretation
        uint32_t ah[2][2][4], al[2][2][4];
        #pragma unroll
        for (int i = 0; i < 2; i++)
            #pragma unroll
            for (int kt = 0; kt < 2; kt++)
                #pragma unroll
                for (int h = 0; h < 2; h++) {       // h: which ntile of the pair (a01 vs a23)
                    float x0 = env[i][2 * kt + h][0], x1 = env[i][2 * kt + h][1];
                    float x2 = env[i][2 * kt + h][2], x3 = env[i][2 * kt + h][3];
                    uint32_t h01 = packbf(x0, x1);
                    uint32_t h23 = packbf(x2, x3);
                    __nv_bfloat162 b01 = *(__nv_bfloat162*)&h01;
                    __nv_bfloat162 b23 = *(__nv_bfloat162*)&h23;
                    ah[i][kt][2 * h]     = h01;
                    ah[i][kt][2 * h + 1] = h23;
                    al[i][kt][2 * h]     = packbf(x0 - __bfloat162float(b01.x),
                                                  x1 - __bfloat162float(b01.y));
                    al[i][kt][2 * h + 1] = packbf(x2 - __bfloat162float(b23.x),
                                                  x3 - __bfloat162float(b23.y));
                }

        float y[2][2][4][4];   // [branch][mtile][ntile][reg]
        #pragma unroll
        for (int c = 0; c < 2; c++)
            #pragma unroll
            for (int i = 0; i < 2; i++)
                #pragma unroll
                for (int j = 0; j < 4; j++)
                    #pragma unroll
                    for (int r = 0; r < 4; r++) y[c][i][j][r] = 0.0f;

        const uint32_t sbase = smem_u32(&sb[s & 1][0]);
        #pragma unroll
        for (int c = 0; c < 2; c++) {
            uint32_t hb = sbase + (2 * c) * TILE_BYTES;
            uint32_t lb = hb + TILE_BYTES;
            #pragma unroll
            for (int j = 0; j < 4; j++) {
                uint32_t bh[4], bl[4];
                ldsm_x4(bh, hb + (uint32_t)(8 * j) * ROWB + lds_off);
                ldsm_x4(bl, lb + (uint32_t)(8 * j) * ROWB + lds_off);
                #pragma unroll
                for (int i = 0; i < 2; i++) {
                    float* acc = y[c][i][j];
                    mma16816(acc, ah[i][0], bh[0], bh[1]);  // Eh*Mh k0
                    mma16816(acc, ah[i][1], bh[2], bh[3]);  // Eh*Mh k1
                    mma16816(acc, al[i][0], bh[0], bh[1]);  // El*Mh k0
                    mma16816(acc, al[i][1], bh[2], bh[3]);  // El*Mh k1
                    mma16816(acc, ah[i][0], bl[0], bl[1]);  // Eh*Ml k0
                    mma16816(acc, ah[i][1], bl[2], bl[3]);  // Eh*Ml k1
                }
            }
        }

        // select branch per row with site-(s+1) config bit
        #pragma unroll
        for (int i = 0; i < 2; i++) {
            const int cA = (int)((mr[2 * i]     >> (s + 1)) & 1ull);
            const int cB = (int)((mr[2 * i + 1] >> (s + 1)) & 1ull);
            #pragma unroll
            for (int j = 0; j < 4; j++) {
                env[i][j][0] = cA ? y[1][i][j][0] : y[0][i][j][0];
                env[i][j][1] = cA ? y[1][i][j][1] : y[0][i][j][1];
                env[i][j][2] = cB ? y[1][i][j][2] : y[0][i][j][2];
                env[i][j][3] = cB ? y[1][i][j][3] : y[0][i][j][3];
            }
        }
        __syncthreads();   // all warps done reading buf[s&1] before it is overwritten
    }

    // final dot with right[:, c63] per row, reduce across the 4 lanes of each row group
    float p[4];
    #pragma unroll
    for (int i = 0; i < 2; i++) {
        const int cA = (int)(mr[2 * i]     >> 63);
        const int cB = (int)(mr[2 * i + 1] >> 63);
        float pa = 0.0f, pb = 0.0f;
        #pragma unroll
        for (int j = 0; j < 4; j++) {
            int n0 = 8 * j + 2 * q;
            pa += env[i][j][0] * rt_s[n0 * 2 + cA] + env[i][j][1] * rt_s[(n0 + 1) * 2 + cA];
            pb += env[i][j][2] * rt_s[n0 * 2 + cB] + env[i][j][3] * rt_s[(n0 + 1) * 2 + cB];
        }
        p[2 * i]     = pa;
        p[2 * i + 1] = pb;
    }
    #pragma unroll
    for (int k = 0; k < 4; k++) {
        p[k] += __shfl_xor_sync(0xFFFFFFFF, p[k], 1);
        p[k] += __shfl_xor_sync(0xFFFFFFFF, p[k], 2);
    }
    if (q == 0) {
        int base = blockIdx.x * TPB + wid * 32 + rowq;
        #pragma unroll
        for (int k = 0; k < 4; k++) out[base + 8 * k] = p[k];
    }
}

extern "C" void kernel_launch(void* const* d_in, const int* in_sizes, int n_in,
                              void* d_out, int out_size) {
    const int*   conf  = (const int*)d_in[0];
    const float* left  = (const float*)d_in[1];
    const float* bulk  = (const float*)d_in[2];
    const float* right = (const float*)d_in[3];
    float*       out   = (float*)d_out;

    prep_kernel<<<NBULK, 256>>>(bulk);
    mps_mma_kernel<<<NCTA, TPB>>>(conf, left, right, out);
}

// round 5
// speedup vs baseline: 3.3901x; 1.0191x over previous
#include <cuda_runtime.h>
#include <cuda_bf16.h>
#include <cstdint>

#define BATCH   32768
#define NSITES  64
#define NBULK   62
#define TPB     128
#define NCTA    (BATCH / TPB)          // 256
#define ROWB    80                     // bytes per SMEM tile row (32 bf16 + 8 pad)
#define TILE_BYTES (32 * ROWB)         // 2560
#define SITE_BYTES (4 * TILE_BYTES)    // M0h, M0l, Dh, Dl = 10240
#define NBUF    4

// Precomputed bf16 hi/lo tiles per site: M0 (hi,lo) and Delta=M1-M0 (hi,lo)
__device__ __align__(256) unsigned char g_btiles[NBULK * SITE_BYTES];

// ---------------- helpers ----------------
__device__ __forceinline__ uint32_t smem_u32(const void* p) {
    uint32_t a;
    asm("{ .reg .u64 t; cvta.to.shared.u64 t, %1; cvt.u32.u64 %0, t; }" : "=r"(a) : "l"(p));
    return a;
}
__device__ __forceinline__ void cp_async16(uint32_t dst, const void* src) {
    asm volatile("cp.async.ca.shared.global [%0], [%1], 16;" :: "r"(dst), "l"(src));
}
__device__ __forceinline__ void cp_commit() { asm volatile("cp.async.commit_group;"); }
template<int N> __device__ __forceinline__ void cp_wait() { asm volatile("cp.async.wait_group %0;" :: "n"(N)); }

__device__ __forceinline__ void ldsm_x4(uint32_t* r, uint32_t addr) {
    asm volatile("ldmatrix.sync.aligned.m8n8.x4.shared.b16 {%0,%1,%2,%3}, [%4];"
        : "=r"(r[0]), "=r"(r[1]), "=r"(r[2]), "=r"(r[3]) : "r"(addr));
}
__device__ __forceinline__ void mma16816(float* d, const uint32_t* a, uint32_t b0, uint32_t b1) {
    asm volatile("mma.sync.aligned.m16n8k16.row.col.f32.bf16.bf16.f32 "
        "{%0,%1,%2,%3}, {%4,%5,%6,%7}, {%8,%9}, {%0,%1,%2,%3};"
        : "+f"(d[0]), "+f"(d[1]), "+f"(d[2]), "+f"(d[3])
        : "r"(a[0]), "r"(a[1]), "r"(a[2]), "r"(a[3]), "r"(b0), "r"(b1));
}
__device__ __forceinline__ uint32_t packbf(float lo, float hi) {
    uint32_t r;
    asm("cvt.rn.bf16x2.f32 %0, %1, %2;" : "=r"(r) : "f"(hi), "f"(lo));
    return r;
}

// ---------------- prep: fp32 bulk -> bf16 hi/lo tiles of M0 and Delta=M1-M0 ----------------
__global__ void prep_kernel(const float* __restrict__ bulk) {
    int s = blockIdx.x;
    const float* base = bulk + s * 2048;            // [d][c][e]
    for (int idx = threadIdx.x; idx < 4096; idx += blockDim.x) {
        int t    = idx >> 10;                        // 0=M0h 1=M0l 2=Dh 3=Dl
        int half = t & 1;
        int rem  = idx & 1023;
        int n    = rem >> 5;                         // e
        int k    = rem & 31;                         // d
        float m0 = base[(k * 2 + 0) * 32 + n];
        float m1 = base[(k * 2 + 1) * 32 + n];
        float x  = (t >> 1) ? (m1 - m0) : m0;
        __nv_bfloat16 bh = __float2bfloat16(x);
        __nv_bfloat16 v  = half ? __float2bfloat16(x - __bfloat162float(bh)) : bh;
        *(__nv_bfloat16*)(g_btiles + (size_t)s * SITE_BYTES + t * TILE_BYTES + n * ROWB + k * 2) = v;
    }
}

// ---------------- main kernel ----------------
__global__ void __launch_bounds__(TPB, 2)
mps_mma_kernel(const int*   __restrict__ conf,
               const float* __restrict__ left,
               const float* __restrict__ right,
               float*       __restrict__ out)
{
    __shared__ __align__(16) unsigned char sb[NBUF][SITE_BYTES];
    __shared__ unsigned long long masks_s[TPB];
    __shared__ float lt_s[64];
    __shared__ float rt_s[64];

    const int tid  = threadIdx.x;
    const int wid  = tid >> 5;
    const int lane = tid & 31;
    const int rowq = lane >> 2;       // 0..7
    const int q    = lane & 3;        // 0..3

    if (tid < 64) { lt_s[tid] = left[tid]; rt_s[tid] = right[tid]; }

    // per-sample config bitmask
    {
        unsigned long long mask = 0;
        const int4* cp4 = (const int4*)(conf + (size_t)(blockIdx.x * TPB + tid) * NSITES);
        #pragma unroll
        for (int i = 0; i < NSITES / 4; i++) {
            int4 v = cp4[i];
            mask |= ((unsigned long long)(v.x & 1) << (4 * i))
                  | ((unsigned long long)(v.y & 1) << (4 * i + 1))
                  | ((unsigned long long)(v.z & 1) << (4 * i + 2))
                  | ((unsigned long long)(v.w & 1) << (4 * i + 3));
        }
        masks_s[tid] = mask;
    }

    // prefetch sites 0 and 1
    #pragma unroll
    for (int p = 0; p < 2; p++) {
        uint32_t dst = smem_u32(&sb[p][0]);
        const unsigned char* src = g_btiles + (size_t)p * SITE_BYTES;
        #pragma unroll
        for (int i = 0; i < 5; i++)
            cp_async16(dst + (tid + i * TPB) * 16, src + (tid + i * TPB) * 16);
        cp_commit();
    }
    __syncthreads();   // masks_s, lt_s, rt_s visible

    // masks of the 4 rows this thread touches
    unsigned long long mr[4];
    #pragma unroll
    for (int k = 0; k < 4; k++) mr[k] = masks_s[wid * 32 + rowq + 8 * k];

    // ---- initial env = left[c0] directly as bf16 hi/lo A fragments ----
    // ah/al[i][kt][reg]: even reg -> row rowq+16i (mask mr[2i]), odd -> rowq+16i+8 (mr[2i+1])
    // k-values: reg pair (2h,2h+1) covers k0 = 16*kt + 8*h + 2q, k0+1
    uint32_t ah[2][2][4], al[2][2][4];
    #pragma unroll
    for (int i = 0; i < 2; i++) {
        const int cA = (int)(mr[2 * i] & 1ull);
        const int cB = (int)(mr[2 * i + 1] & 1ull);
        #pragma unroll
        for (int kt = 0; kt < 2; kt++)
            #pragma unroll
            for (int h = 0; h < 2; h++) {
                int k0 = 16 * kt + 8 * h + 2 * q;
                float xA0 = lt_s[cA * 32 + k0], xA1 = lt_s[cA * 32 + k0 + 1];
                float xB0 = lt_s[cB * 32 + k0], xB1 = lt_s[cB * 32 + k0 + 1];
                uint32_t hA = packbf(xA0, xA1);
                uint32_t hB = packbf(xB0, xB1);
                __nv_bfloat162 bA = *(__nv_bfloat162*)&hA;
                __nv_bfloat162 bB = *(__nv_bfloat162*)&hB;
                ah[i][kt][2 * h]     = hA;
                ah[i][kt][2 * h + 1] = hB;
                al[i][kt][2 * h]     = packbf(xA0 - __bfloat162float(bA.x),
                                              xA1 - __bfloat162float(bA.y));
                al[i][kt][2 * h + 1] = packbf(xB0 - __bfloat162float(bB.x),
                                              xB1 - __bfloat162float(bB.y));
            }
    }

    const uint32_t lds_off = (uint32_t)((lane & 7) * ROWB + (lane >> 3) * 16);
    float acc[2][4][4];

    for (int s = 0; s < NBULK; s++) {
        // distance-2 prefetch into 4-deep ring
        if (s + 2 < NBULK) {
            uint32_t dst = smem_u32(&sb[(s + 2) & 3][0]);
            const unsigned char* src = g_btiles + (size_t)(s + 2) * SITE_BYTES;
            #pragma unroll
            for (int i = 0; i < 5; i++)
                cp_async16(dst + (tid + i * TPB) * 16, src + (tid + i * TPB) * 16);
            cp_commit();
            cp_wait<2>();
        } else if (s + 1 < NBULK) {
            cp_wait<1>();
        } else {
            cp_wait<0>();
        }
        __syncthreads();   // single barrier per site: publish site-s tiles

        #pragma unroll
        for (int i = 0; i < 2; i++)
            #pragma unroll
            for (int j = 0; j < 4; j++)
                #pragma unroll
                for (int r = 0; r < 4; r++) acc[i][j][r] = 0.0f;

        const uint32_t sbase = smem_u32(&sb[s & 3][0]);

        // ---- pass 1: acc += E * M0 (3 precision terms) ----
        #pragma unroll
        for (int j = 0; j < 4; j++) {
            uint32_t bh[4], bl[4];
            ldsm_x4(bh, sbase + 0 * TILE_BYTES + (uint32_t)(8 * j) * ROWB + lds_off);
            ldsm_x4(bl, sbase + 1 * TILE_BYTES + (uint32_t)(8 * j) * ROWB + lds_off);
            #pragma unroll
            for (int i = 0; i < 2; i++) {
                float* a = acc[i][j];
                mma16816(a, ah[i][0], bh[0], bh[1]);
                mma16816(a, ah[i][1], bh[2], bh[3]);
                mma16816(a, al[i][0], bh[0], bh[1]);
                mma16816(a, al[i][1], bh[2], bh[3]);
                mma16816(a, ah[i][0], bl[0], bl[1]);
                mma16816(a, ah[i][1], bl[2], bl[3]);
            }
        }

        // ---- mask A fragments in place with site-(s+1) bits ----
        {
            const uint32_t c0 = (uint32_t)((mr[0] >> (s + 1)) & 1ull);
            const uint32_t c1 = (uint32_t)((mr[1] >> (s + 1)) & 1ull);
            const uint32_t c2 = (uint32_t)((mr[2] >> (s + 1)) & 1ull);
            const uint32_t c3 = (uint32_t)((mr[3] >> (s + 1)) & 1ull);
            #pragma unroll
            for (int kt = 0; kt < 2; kt++)
                #pragma unroll
                for (int h = 0; h < 2; h++) {
                    ah[0][kt][2*h]   = c0 ? ah[0][kt][2*h]   : 0u;
                    al[0][kt][2*h]   = c0 ? al[0][kt][2*h]   : 0u;
                    ah[0][kt][2*h+1] = c1 ? ah[0][kt][2*h+1] : 0u;
                    al[0][kt][2*h+1] = c1 ? al[0][kt][2*h+1] : 0u;
                    ah[1][kt][2*h]   = c2 ? ah[1][kt][2*h]   : 0u;
                    al[1][kt][2*h]   = c2 ? al[1][kt][2*h]   : 0u;
                    ah[1][kt][2*h+1] = c3 ? ah[1][kt][2*h+1] : 0u;
                    al[1][kt][2*h+1] = c3 ? al[1][kt][2*h+1] : 0u;
                }
        }

        // ---- pass 2: acc += E_masked * Delta (3 precision terms) ----
        #pragma unroll
        for (int j = 0; j < 4; j++) {
            uint32_t bh[4], bl[4];
            ldsm_x4(bh, sbase + 2 * TILE_BYTES + (uint32_t)(8 * j) * ROWB + lds_off);
            ldsm_x4(bl, sbase + 3 * TILE_BYTES + (uint32_t)(8 * j) * ROWB + lds_off);
            #pragma unroll
            for (int i = 0; i < 2; i++) {
                float* a = acc[i][j];
                mma16816(a, ah[i][0], bh[0], bh[1]);
                mma16816(a, ah[i][1], bh[2], bh[3]);
                mma16816(a, al[i][0], bh[0], bh[1]);
                mma16816(a, al[i][1], bh[2], bh[3]);
                mma16816(a, ah[i][0], bl[0], bl[1]);
                mma16816(a, ah[i][1], bl[2], bl[3]);
            }
        }

        // ---- split selected env (acc) -> next A fragments ----
        if (s + 1 < NBULK) {
            #pragma unroll
            for (int i = 0; i < 2; i++)
                #pragma unroll
                for (int kt = 0; kt < 2; kt++)
                    #pragma unroll
                    for (int h = 0; h < 2; h++) {
                        float x0 = acc[i][2 * kt + h][0], x1 = acc[i][2 * kt + h][1];
                        float x2 = acc[i][2 * kt + h][2], x3 = acc[i][2 * kt + h][3];
                        uint32_t h01 = packbf(x0, x1);
                        uint32_t h23 = packbf(x2, x3);
                        __nv_bfloat162 b01 = *(__nv_bfloat162*)&h01;
                        __nv_bfloat162 b23 = *(__nv_bfloat162*)&h23;
                        ah[i][kt][2 * h]     = h01;
                        ah[i][kt][2 * h + 1] = h23;
                        al[i][kt][2 * h]     = packbf(x0 - __bfloat162float(b01.x),
                                                      x1 - __bfloat162float(b01.y));
                        al[i][kt][2 * h + 1] = packbf(x2 - __bfloat162float(b23.x),
                                                      x3 - __bfloat162float(b23.y));
                    }
        }
        // no trailing barrier: 4-deep ring + distance-2 prefetch is safe under 1-site skew
    }

    // ---- final dot with right[:, c63]; reduce across the 4 lanes of each row group ----
    float p[4];
    #pragma unroll
    for (int i = 0; i < 2; i++) {
        const int cA = (int)(mr[2 * i]     >> 63);
        const int cB = (int)(mr[2 * i + 1] >> 63);
        float pa = 0.0f, pb = 0.0f;
        #pragma unroll
        for (int j = 0; j < 4; j++) {
            int n0 = 8 * j + 2 * q;
            pa += acc[i][j][0] * rt_s[n0 * 2 + cA] + acc[i][j][1] * rt_s[(n0 + 1) * 2 + cA];
            pb += acc[i][j][2] * rt_s[n0 * 2 + cB] + acc[i][j][3] * rt_s[(n0 + 1) * 2 + cB];
        }
        p[2 * i]     = pa;
        p[2 * i + 1] = pb;
    }
    #pragma unroll
    for (int k = 0; k < 4; k++) {
        p[k] += __shfl_xor_sync(0xFFFFFFFF, p[k], 1);
        p[k] += __shfl_xor_sync(0xFFFFFFFF, p[k], 2);
    }
    if (q == 0) {
        int base = blockIdx.x * TPB + wid * 32 + rowq;
        #pragma unroll
        for (int k = 0; k < 4; k++) out[base + 8 * k] = p[k];
    }
}

extern "C" void kernel_launch(void* const* d_in, const int* in_sizes, int n_in,
                              void* d_out, int out_size) {
    const int*   conf  = (const int*)d_in[0];
    const float* left  = (const float*)d_in[1];
    const float* bulk  = (const float*)d_in[2];
    const float* right = (const float*)d_in[3];
    float*       out   = (float*)d_out;

    prep_kernel<<<NBULK, 256>>>(bulk);
    mps_mma_kernel<<<NCTA, TPB>>>(conf, left, right, out);
}